// round 7
// baseline (speedup 1.0000x reference)
#include <cuda_runtime.h>
#include <cuda_fp16.h>
#include <cstdint>

// ---------------- Problem constants ----------------
#define IN_F   512
#define OUT_F  512
#define NEXP   8
#define NGRP   32
#define TPG    2048
#define NTOK   (NGRP * TPG)

// ---------------- Scratch (no cudaMalloc allowed) ----------------
__device__ __align__(16) __half g_w[(size_t)NGRP * OUT_F * IN_F];   // 16.7 MB fp16 mixed weights
__device__ float g_bias_mix[NGRP * OUT_F];

// ---------------- helpers ----------------
static __device__ __forceinline__ uint32_t smem_u32(const void* p) {
    uint32_t a;
    asm("{ .reg .u64 t; cvta.to.shared.u64 t, %1; cvt.u32.u64 %0, t; }"
        : "=r"(a) : "l"(p));
    return a;
}

static __device__ __forceinline__ void cp_async16(uint32_t dst, const void* src) {
    asm volatile("cp.async.ca.shared.global [%0], [%1], 16;"
                 :: "r"(dst), "l"(src) : "memory");
}
static __device__ __forceinline__ void cp_async_commit() {
    asm volatile("cp.async.commit_group;" ::: "memory");
}
static __device__ __forceinline__ void cp_async_wait0() {
    asm volatile("cp.async.wait_group 0;" ::: "memory");
}

static __device__ __forceinline__ void ldm_x4(uint32_t* r, uint32_t addr) {
    asm volatile("ldmatrix.sync.aligned.m8n8.x4.shared.b16 {%0,%1,%2,%3}, [%4];"
                 : "=r"(r[0]), "=r"(r[1]), "=r"(r[2]), "=r"(r[3]) : "r"(addr));
}

static __device__ __forceinline__ void mma_16816(float* c, const uint32_t* a, const uint32_t* b) {
    asm volatile(
        "mma.sync.aligned.m16n8k16.row.col.f32.f16.f16.f32 "
        "{%0,%1,%2,%3}, {%4,%5,%6,%7}, {%8,%9}, {%0,%1,%2,%3};"
        : "+f"(c[0]), "+f"(c[1]), "+f"(c[2]), "+f"(c[3])
        : "r"(a[0]), "r"(a[1]), "r"(a[2]), "r"(a[3]), "r"(b[0]), "r"(b[1]));
}

// Split fp32 pair into hi fp16x2 and lo (residual) fp16x2
static __device__ __forceinline__ void split_pack(float a, float b, uint32_t& h, uint32_t& l)
{
    __half2 hv = __floats2half2_rn(a, b);
    float2 hf = __half22float2(hv);
    __half2 lv = __floats2half2_rn(a - hf.x, b - hf.y);
    h = *reinterpret_cast<uint32_t*>(&hv);
    l = *reinterpret_cast<uint32_t*>(&lv);
}

// ---------------- Kernel 1: mix expert weights -> fp16 ----------------
// grid 256 x block 256: each thread owns one float4 of the [512,512] weight
// matrix and loops over the 32 groups (expert weights stay in registers).
__global__ void mix_weights_kernel(const float* __restrict__ coeff,
                                   const float* __restrict__ we,
                                   const float* __restrict__ ws)
{
    __shared__ float c_sm[NGRP * NEXP];  // 256 floats
    int t = threadIdx.x;
    c_sm[t] = coeff[t];
    __syncthreads();

    int p = blockIdx.x * 256 + t;            // float4 index 0..65535
    const float4* ws4 = reinterpret_cast<const float4*>(ws);
    const float4* we4 = reinterpret_cast<const float4*>(we);
    float4 s = ws4[p];
    float4 e4[NEXP];
#pragma unroll
    for (int e = 0; e < NEXP; e++) e4[e] = we4[e * 65536 + p];

    for (int g = 0; g < NGRP; g++) {
        const float* cg = c_sm + g * NEXP;
        float4 acc = s;
#pragma unroll
        for (int e = 0; e < NEXP; e++) {
            acc.x = fmaf(cg[e], e4[e].x, acc.x);
            acc.y = fmaf(cg[e], e4[e].y, acc.y);
            acc.z = fmaf(cg[e], e4[e].z, acc.z);
            acc.w = fmaf(cg[e], e4[e].w, acc.w);
        }
        __half2 p01 = __floats2half2_rn(acc.x, acc.y);
        __half2 p23 = __floats2half2_rn(acc.z, acc.w);
        uint2 packed = make_uint2(*reinterpret_cast<uint32_t*>(&p01),
                                  *reinterpret_cast<uint32_t*>(&p23));
        reinterpret_cast<uint2*>(g_w)[(size_t)g * 65536 + p] = packed;
    }
}

// ---------------- Kernel 2: mix bias ----------------
__global__ void mix_bias_kernel(const float* __restrict__ coeff,
                                const float* __restrict__ be,
                                const float* __restrict__ bs)
{
    int g = blockIdx.x;
    int n = threadIdx.x;  // 512
    float acc = bs[n];
#pragma unroll
    for (int e = 0; e < NEXP; e++)
        acc = fmaf(coeff[g * NEXP + e], be[e * OUT_F + n], acc);
    g_bias_mix[g * OUT_F + n] = acc;
}

// ---------------- Kernel 3: grouped GEMM, mma.sync fp16 hi/lo split ----------------
// CTA tile 128x128, 8 warps, warp tile 32x64 (warp grid 4m x 2n).
// K = 512 in 16 chunks of 32. A (x) is loaded fp32 and split to hi/lo fp16 on
// the fly; W comes from precomputed fp16 scratch via cp.async.
// SMEM rows use 80B stride -> ldmatrix phases are bank-conflict-free
// (8 consecutive rows at stride 80 hit 8 distinct 16B granules mod 128).
#define ROWB 80

__global__ void __launch_bounds__(256, 2)
moe_gemm_kernel(const float* __restrict__ x, float* __restrict__ out)
{
    __shared__ __align__(128) uint8_t sAh[128 * ROWB];
    __shared__ __align__(128) uint8_t sAl[128 * ROWB];
    __shared__ __align__(128) uint8_t sW [128 * ROWB];

    const int tid  = threadIdx.x;
    const int lane = tid & 31;
    const int wid  = tid >> 5;
    const int wm   = (wid & 3) * 32;   // warp m offset
    const int wn   = (wid >> 2) * 64;  // warp n offset

    const int bx = blockIdx.x;          // 0..2047
    const int g  = bx >> 6;             // 64 tiles per group
    const int mt = (bx >> 2) & 15;
    const int nt = bx & 3;
    const int m0 = g * TPG + mt * 128;
    const int n0 = nt * 128;

    const uint32_t sAh_b = smem_u32(sAh);
    const uint32_t sAl_b = smem_u32(sAl);
    const uint32_t sW_b  = smem_u32(sW);

    const __half* wg = g_w + (size_t)g * OUT_F * IN_F + (size_t)n0 * IN_F;

    float acc[2][8][4];
#pragma unroll
    for (int i = 0; i < 2; i++)
#pragma unroll
        for (int j = 0; j < 8; j++)
#pragma unroll
            for (int kk = 0; kk < 4; kk++) acc[i][j][kk] = 0.0f;

    // per-thread fixed roles for loading
    const int arow = tid >> 1;          // A row 0..127
    const int ahalf = tid & 1;          // which 16-float half of the 32-wide chunk

    for (int kc = 0; kc < 16; kc++) {
        const int k0 = kc * 32;

        // ---- W tile via cp.async: 128 rows x 64B = 512 x 16B ops ----
#pragma unroll
        for (int u = 0; u < 2; u++) {
            const int lin = tid + u * 256;     // 0..511
            const int wr  = lin >> 2;          // row
            const int wsg = lin & 3;           // 16B segment
            cp_async16(sW_b + wr * ROWB + wsg * 16,
                       wg + (size_t)wr * IN_F + k0 + wsg * 8);
        }
        cp_async_commit();

        // ---- A tile: LDG fp32, split hi/lo fp16, STS ----
        const float4* src = reinterpret_cast<const float4*>(
            x + (size_t)(m0 + arow) * IN_F + k0 + ahalf * 16);
        float4 v0 = src[0], v1 = src[1], v2 = src[2], v3 = src[3];
        uint32_t h[8], l[8];
        split_pack(v0.x, v0.y, h[0], l[0]);
        split_pack(v0.z, v0.w, h[1], l[1]);
        split_pack(v1.x, v1.y, h[2], l[2]);
        split_pack(v1.z, v1.w, h[3], l[3]);
        split_pack(v2.x, v2.y, h[4], l[4]);
        split_pack(v2.z, v2.w, h[5], l[5]);
        split_pack(v3.x, v3.y, h[6], l[6]);
        split_pack(v3.z, v3.w, h[7], l[7]);
        const uint32_t aoff = arow * ROWB + ahalf * 32;
        *reinterpret_cast<uint4*>(sAh + aoff)      = make_uint4(h[0], h[1], h[2], h[3]);
        *reinterpret_cast<uint4*>(sAh + aoff + 16) = make_uint4(h[4], h[5], h[6], h[7]);
        *reinterpret_cast<uint4*>(sAl + aoff)      = make_uint4(l[0], l[1], l[2], l[3]);
        *reinterpret_cast<uint4*>(sAl + aoff + 16) = make_uint4(l[4], l[5], l[6], l[7]);

        cp_async_wait0();
        __syncthreads();

        // ---- compute: 2 k16 steps ----
#pragma unroll
        for (int s = 0; s < 2; s++) {
            // B fragments: 4x ldmatrix.x4, each covers two n8 tiles (k-lo,k-hi)
            uint32_t bfr[16];
#pragma unroll
            for (int p = 0; p < 4; p++) {
                const uint32_t baddr = sW_b
                    + (uint32_t)(wn + p * 16 + (lane >> 4) * 8 + (lane & 7)) * ROWB
                    + s * 32 + ((lane >> 3) & 1) * 16;
                ldm_x4(bfr + p * 4, baddr);
            }
            // A fragments: hi and lo, 2 m16 tiles each
            uint32_t ah[2][4], al[2][4];
#pragma unroll
            for (int m = 0; m < 2; m++) {
                const uint32_t arow_l = (uint32_t)(wm + m * 16 + (lane & 15)) * ROWB
                                      + s * 32 + (lane >> 4) * 16;
                ldm_x4(ah[m], sAh_b + arow_l);
                ldm_x4(al[m], sAl_b + arow_l);
            }
#pragma unroll
            for (int m = 0; m < 2; m++) {
#pragma unroll
                for (int n = 0; n < 8; n++) {
                    const uint32_t* bp = bfr + (n >> 1) * 4 + (n & 1) * 2;
                    mma_16816(acc[m][n], ah[m], bp);
                    mma_16816(acc[m][n], al[m], bp);
                }
            }
        }
        __syncthreads();
    }

    // ---- epilogue: bias add + direct float2 stores ----
    const float* bias = g_bias_mix + g * OUT_F + n0;
    const int crow = lane >> 2;
    const int ccol2 = 2 * (lane & 3);
#pragma unroll
    for (int m = 0; m < 2; m++) {
        const int row = m0 + wm + m * 16 + crow;
#pragma unroll
        for (int n = 0; n < 8; n++) {
            const int col = wn + n * 8 + ccol2;
            const float2 bv = *reinterpret_cast<const float2*>(bias + col);
            float2 o0 = make_float2(acc[m][n][0] + bv.x, acc[m][n][1] + bv.y);
            float2 o1 = make_float2(acc[m][n][2] + bv.x, acc[m][n][3] + bv.y);
            *reinterpret_cast<float2*>(out + (size_t)row * OUT_F + n0 + col) = o0;
            *reinterpret_cast<float2*>(out + (size_t)(row + 8) * OUT_F + n0 + col) = o1;
        }
    }
}

// ---------------- Launch ----------------
extern "C" void kernel_launch(void* const* d_in, const int* in_sizes, int n_in,
                              void* d_out, int out_size)
{
    const float* x     = (const float*)d_in[0];
    const float* coeff = (const float*)d_in[1];
    const float* we    = (const float*)d_in[2];
    const float* be    = (const float*)d_in[3];
    const float* ws    = (const float*)d_in[4];
    const float* bs    = (const float*)d_in[5];
    float* out = (float*)d_out;

    mix_weights_kernel<<<256, 256>>>(coeff, we, ws);
    mix_bias_kernel<<<NGRP, OUT_F>>>(coeff, be, bs);
    moe_gemm_kernel<<<NGRP * 16 * 4, 256>>>(x, out);
}